// round 4
// baseline (speedup 1.0000x reference)
#include <cuda_runtime.h>
#include <math.h>
#include <stdint.h>

#define BB 4
#define CC 512
#define NN 4096   // H*W
#define DD 512
#define SCALE 0.04419417382415922f   // 1/sqrt(512)

// Scratch (__device__ globals; no allocation allowed)
__device__ float g_Xt[(size_t)BB * NN * CC];     // x transposed: [b][t][c]
__device__ float g_Q [(size_t)BB * NN * DD];     // [b][t][d]
__device__ float g_K [(size_t)BB * NN * DD];     // [b][t][d]
__device__ float g_Vt[(size_t)BB * DD * NN];     // [b][d][t]  (V transposed)
__device__ float g_S [(size_t)BB * NN * NN];     // [b][i][j]

// ---------------------------------------------------------------------------
// helpers
// ---------------------------------------------------------------------------
__device__ __forceinline__ uint32_t f2tf32(float x) {
    uint32_t r;
    asm("cvt.rna.tf32.f32 %0, %1;\n" : "=r"(r) : "f"(x));
    return r;
}

__device__ __forceinline__ void mma_tf32(float c[4],
    uint32_t a0, uint32_t a1, uint32_t a2, uint32_t a3,
    uint32_t b0, uint32_t b1)
{
    asm volatile(
        "mma.sync.aligned.m16n8k8.row.col.f32.tf32.tf32.f32 "
        "{%0,%1,%2,%3}, {%4,%5,%6,%7}, {%8,%9}, {%0,%1,%2,%3};\n"
        : "+f"(c[0]), "+f"(c[1]), "+f"(c[2]), "+f"(c[3])
        : "r"(a0), "r"(a1), "r"(a2), "r"(a3), "r"(b0), "r"(b1));
}

// ---------------------------------------------------------------------------
// x (B,C,N) -> Xt (B,N,C)
// ---------------------------------------------------------------------------
__global__ __launch_bounds__(256) void transpose_x(const float* __restrict__ x,
                                                   float* __restrict__ xt)
{
    __shared__ float tile[32][33];
    int b  = blockIdx.z;
    int t0 = blockIdx.x * 32;
    int c0 = blockIdx.y * 32;
    const float* in = x + (size_t)b * CC * NN;
    float* out = xt + (size_t)b * NN * CC;

    #pragma unroll
    for (int i = threadIdx.y; i < 32; i += 8)
        tile[i][threadIdx.x] = in[(size_t)(c0 + i) * NN + t0 + threadIdx.x];
    __syncthreads();
    #pragma unroll
    for (int i = threadIdx.y; i < 32; i += 8)
        out[(size_t)(t0 + i) * CC + c0 + threadIdx.x] = tile[threadIdx.x][i];
}

// ---------------------------------------------------------------------------
// Generic tf32 tensor-core GEMM:  C[m][n] = scale * sum_k A[m][k] * B[n][k]
// A row stride = K, B row stride = K, C row stride = N. Batched via grid.z.
// Block tile 128x128, k-tile 32, 256 threads (8 warps, 2x4 warp grid, 64x32
// warp tiles of m16n8k8 atoms). Register-double-buffered gmem loads.
// ---------------------------------------------------------------------------
#define LDK 36  // padded smem k-stride (words): banks (4r+c)%32 all distinct

__global__ __launch_bounds__(256, 1) void gemm_tc(
    const float* __restrict__ A, const float* __restrict__ B, float* __restrict__ C,
    int M, int N, int K,
    size_t sA, size_t sB, size_t sC, float scale)
{
    __shared__ uint32_t As[128 * LDK];
    __shared__ uint32_t Bs[128 * LDK];

    const float* Ab = A + blockIdx.z * sA + (size_t)(blockIdx.y * 128) * K;
    const float* Bb = B + blockIdx.z * sB + (size_t)(blockIdx.x * 128) * K;
    float* Cb = C + blockIdx.z * sC;
    int m0 = blockIdx.y * 128, n0 = blockIdx.x * 128;

    int tid  = threadIdx.x;
    int lane = tid & 31;
    int warp = tid >> 5;
    int wm = (warp >> 2) * 64;    // warp m offset (0,64)
    int wn = (warp & 3) * 32;     // warp n offset (0,32,64,96)

    float acc[4][4][4] = {};      // [m-atom][n-atom][frag]

    // gmem tile load mapping: 128 rows x 32 k per operand, float4 per thread x4
    int lr = tid >> 3;            // 0..31 (row group)
    int lk = (tid & 7) * 4;       // k offset 0..28

    float4 pa[4], pb[4];
    #pragma unroll
    for (int it = 0; it < 4; it++) {
        pa[it] = *(const float4*)&Ab[(size_t)(lr + it * 32) * K + lk];
        pb[it] = *(const float4*)&Bb[(size_t)(lr + it * 32) * K + lk];
    }

    for (int k0 = 0; k0 < K; k0 += 32) {
        // regs -> smem (convert to tf32)
        #pragma unroll
        for (int it = 0; it < 4; it++) {
            uint32_t* a = &As[(lr + it * 32) * LDK + lk];
            a[0] = f2tf32(pa[it].x); a[1] = f2tf32(pa[it].y);
            a[2] = f2tf32(pa[it].z); a[3] = f2tf32(pa[it].w);
            uint32_t* b = &Bs[(lr + it * 32) * LDK + lk];
            b[0] = f2tf32(pb[it].x); b[1] = f2tf32(pb[it].y);
            b[2] = f2tf32(pb[it].z); b[3] = f2tf32(pb[it].w);
        }
        __syncthreads();

        // prefetch next k-tile
        if (k0 + 32 < K) {
            #pragma unroll
            for (int it = 0; it < 4; it++) {
                pa[it] = *(const float4*)&Ab[(size_t)(lr + it * 32) * K + k0 + 32 + lk];
                pb[it] = *(const float4*)&Bb[(size_t)(lr + it * 32) * K + k0 + 32 + lk];
            }
        }

        int r = lane >> 2, c = lane & 3;
        #pragma unroll
        for (int kk = 0; kk < 32; kk += 8) {
            uint32_t af[4][4], bf[4][2];
            #pragma unroll
            for (int ma = 0; ma < 4; ma++) {
                int row = wm + ma * 16;
                af[ma][0] = As[(row + r)     * LDK + kk + c];
                af[ma][1] = As[(row + r + 8) * LDK + kk + c];
                af[ma][2] = As[(row + r)     * LDK + kk + c + 4];
                af[ma][3] = As[(row + r + 8) * LDK + kk + c + 4];
            }
            #pragma unroll
            for (int na = 0; na < 4; na++) {
                int col = wn + na * 8;
                bf[na][0] = Bs[(col + r) * LDK + kk + c];       // b0: k=lane%4, n=lane/4
                bf[na][1] = Bs[(col + r) * LDK + kk + c + 4];   // b1: k=lane%4+4
            }
            #pragma unroll
            for (int ma = 0; ma < 4; ma++)
                #pragma unroll
                for (int na = 0; na < 4; na++)
                    mma_tf32(acc[ma][na],
                             af[ma][0], af[ma][1], af[ma][2], af[ma][3],
                             bf[na][0], bf[na][1]);
        }
        __syncthreads();
    }

    // epilogue: c0 (r, 2c), c1 (r, 2c+1), c2 (r+8, 2c), c3 (r+8, 2c+1)
    int r = lane >> 2, cc = (lane & 3) * 2;
    #pragma unroll
    for (int ma = 0; ma < 4; ma++)
        #pragma unroll
        for (int na = 0; na < 4; na++) {
            int row = m0 + wm + ma * 16 + r;
            int col = n0 + wn + na * 8 + cc;
            float2 v0 = make_float2(acc[ma][na][0] * scale, acc[ma][na][1] * scale);
            float2 v1 = make_float2(acc[ma][na][2] * scale, acc[ma][na][3] * scale);
            *(float2*)&Cb[(size_t)row * N + col]       = v0;
            *(float2*)&Cb[(size_t)(row + 8) * N + col] = v1;
        }
}

// ---------------------------------------------------------------------------
// In-place row softmax over S
// ---------------------------------------------------------------------------
__global__ __launch_bounds__(256) void softmax_kernel()
{
    __shared__ float red[256];
    float* row = g_S + ((size_t)blockIdx.y * NN + blockIdx.x) * NN;
    int t = threadIdx.x;

    float vals[16];
    float m = -1e30f;
    #pragma unroll
    for (int u = 0; u < 16; u++) {
        vals[u] = row[t + u * 256];
        m = fmaxf(m, vals[u]);
    }
    red[t] = m;
    __syncthreads();
    for (int s = 128; s > 0; s >>= 1) {
        if (t < s) red[t] = fmaxf(red[t], red[t + s]);
        __syncthreads();
    }
    m = red[0];
    __syncthreads();

    float sum = 0.f;
    #pragma unroll
    for (int u = 0; u < 16; u++) {
        vals[u] = __expf(vals[u] - m);
        sum += vals[u];
    }
    red[t] = sum;
    __syncthreads();
    for (int s = 128; s > 0; s >>= 1) {
        if (t < s) red[t] += red[t + s];
        __syncthreads();
    }
    float inv = 1.0f / red[0];
    #pragma unroll
    for (int u = 0; u < 16; u++)
        row[t + u * 256] = vals[u] * inv;
}

// ---------------------------------------------------------------------------
// scores_out[b][j] = sum_i S[b][i][j], split over i with atomics
// ---------------------------------------------------------------------------
__global__ __launch_bounds__(256) void zero_scores(float* __restrict__ scores_out)
{
    int idx = blockIdx.x * 256 + threadIdx.x;
    if (idx < BB * NN) scores_out[idx] = 0.f;
}

__global__ __launch_bounds__(256) void colsum_kernel(float* __restrict__ scores_out)
{
    int b = blockIdx.z;
    int j = blockIdx.x * 256 + threadIdx.x;
    int i0 = blockIdx.y * 256;
    const float* Sb = g_S + (size_t)b * NN * NN;
    float s = 0.f;
    #pragma unroll 8
    for (int i = i0; i < i0 + 256; i++)
        s += Sb[(size_t)i * NN + j];
    atomicAdd(&scores_out[(size_t)b * NN + j], s);
}

// ---------------------------------------------------------------------------
extern "C" void kernel_launch(void* const* d_in, const int* in_sizes, int n_in,
                              void* d_out, int out_size)
{
    const float* x  = (const float*)d_in[0];
    const float* Wk = (const float*)d_in[1];
    const float* Wq = (const float*)d_in[2];
    const float* Wv = (const float*)d_in[3];

    float* out        = (float*)d_out;                 // (B, D, H, W) = [b][d][t]
    float* scores_out = out + (size_t)BB * DD * NN;    // (B, 1, H, W)

    float *Xt, *Q, *K, *Vt, *S;
    cudaGetSymbolAddress((void**)&Xt, g_Xt);
    cudaGetSymbolAddress((void**)&Q,  g_Q);
    cudaGetSymbolAddress((void**)&K,  g_K);
    cudaGetSymbolAddress((void**)&Vt, g_Vt);
    cudaGetSymbolAddress((void**)&S,  g_S);

    // 1) transpose x -> Xt[b][t][c]
    transpose_x<<<dim3(NN / 32, CC / 32, BB), dim3(32, 8)>>>(x, Xt);

    // 2) Q[t][d] = Xt . Wq^T   (M=N tokens, N=DD, K=CC)
    gemm_tc<<<dim3(DD / 128, NN / 128, BB), 256>>>(
        Xt, Wq, Q, NN, DD, CC,
        (size_t)NN * CC, 0, (size_t)NN * DD, 1.0f);
    // 3) K[t][d] = Xt . Wk^T
    gemm_tc<<<dim3(DD / 128, NN / 128, BB), 256>>>(
        Xt, Wk, K, NN, DD, CC,
        (size_t)NN * CC, 0, (size_t)NN * DD, 1.0f);
    // 4) Vt[d][t] = Wv . Xt^T   (operands swapped -> transposed V for free)
    gemm_tc<<<dim3(NN / 128, DD / 128, BB), 256>>>(
        Wv, Xt, Vt, DD, NN, CC,
        0, (size_t)NN * CC, (size_t)DD * NN, 1.0f);

    // 5) S[i][j] = SCALE * Q . K^T
    gemm_tc<<<dim3(NN / 128, NN / 128, BB), 256>>>(
        Q, K, S, NN, NN, DD,
        (size_t)NN * DD, (size_t)NN * DD, (size_t)NN * NN, SCALE);

    // 6) softmax rows of S in place
    softmax_kernel<<<dim3(NN, BB), 256>>>();

    // 7) out[d][t] = Vt . S^T  (K = tokens j)
    gemm_tc<<<dim3(NN / 128, DD / 128, BB), 256>>>(
        Vt, S, out, DD, NN, NN,
        (size_t)DD * NN, (size_t)NN * NN, (size_t)DD * NN, 1.0f);

    // 8) scores_out[b][j] = sum_i S[b][i][j]
    zero_scores<<<(BB * NN + 255) / 256, 256>>>(scores_out);
    colsum_kernel<<<dim3(NN / 256, NN / 256, BB), 256>>>(scores_out);
}

// round 5
// speedup vs baseline: 1.0004x; 1.0004x over previous
#include <cuda_runtime.h>
#include <math.h>
#include <stdint.h>

#define BB 4
#define CC 512
#define NN 4096   // H*W
#define DD 512
#define SCALE 0.04419417382415922f   // 1/sqrt(512)

// Scratch (__device__ globals; no allocation allowed)
__device__ float g_Xt[(size_t)BB * NN * CC];     // x transposed: [b][t][c]
__device__ float g_Q [(size_t)BB * NN * DD];     // [b][t][d]
__device__ float g_K [(size_t)BB * NN * DD];     // [b][t][d]
__device__ float g_Vt[(size_t)BB * DD * NN];     // [b][d][t]  (V transposed)
__device__ float g_S [(size_t)BB * NN * NN];     // [b][i][j]

// ---------------------------------------------------------------------------
// helpers
// ---------------------------------------------------------------------------
__device__ __forceinline__ uint32_t f2tf32(float x) {
    uint32_t r;
    asm("cvt.rna.tf32.f32 %0, %1;\n" : "=r"(r) : "f"(x));
    return r;
}

__device__ __forceinline__ void mma_tf32(float c[4],
    uint32_t a0, uint32_t a1, uint32_t a2, uint32_t a3,
    uint32_t b0, uint32_t b1)
{
    asm volatile(
        "mma.sync.aligned.m16n8k8.row.col.f32.tf32.tf32.f32 "
        "{%0,%1,%2,%3}, {%4,%5,%6,%7}, {%8,%9}, {%0,%1,%2,%3};\n"
        : "+f"(c[0]), "+f"(c[1]), "+f"(c[2]), "+f"(c[3])
        : "r"(a0), "r"(a1), "r"(a2), "r"(a3), "r"(b0), "r"(b1));
}

// ---------------------------------------------------------------------------
// x (B,C,N) -> Xt (B,N,C)
// ---------------------------------------------------------------------------
__global__ __launch_bounds__(256) void transpose_x(const float* __restrict__ x,
                                                   float* __restrict__ xt)
{
    __shared__ float tile[32][33];
    int b  = blockIdx.z;
    int t0 = blockIdx.x * 32;
    int c0 = blockIdx.y * 32;
    const float* in = x + (size_t)b * CC * NN;
    float* out = xt + (size_t)b * NN * CC;

    #pragma unroll
    for (int i = threadIdx.y; i < 32; i += 8)
        tile[i][threadIdx.x] = in[(size_t)(c0 + i) * NN + t0 + threadIdx.x];
    __syncthreads();
    #pragma unroll
    for (int i = threadIdx.y; i < 32; i += 8)
        out[(size_t)(t0 + i) * CC + c0 + threadIdx.x] = tile[threadIdx.x][i];
}

// ---------------------------------------------------------------------------
// Generic tf32 tensor-core GEMM:  C[m][n] = scale * sum_k A[m][k] * B[n][k]
// A row stride = K, B row stride = K, C row stride = N. Batched via grid.z.
// Block tile 128x128, k-tile 32, 256 threads (8 warps, 2x4 warp grid, 64x32
// warp tiles of m16n8k8 atoms). Register-double-buffered gmem loads.
// ---------------------------------------------------------------------------
#define LDK 36  // padded smem k-stride (words): banks (4r+c)%32 all distinct

__global__ __launch_bounds__(256, 1) void gemm_tc(
    const float* __restrict__ A, const float* __restrict__ B, float* __restrict__ C,
    int M, int N, int K,
    size_t sA, size_t sB, size_t sC, float scale)
{
    __shared__ uint32_t As[128 * LDK];
    __shared__ uint32_t Bs[128 * LDK];

    const float* Ab = A + blockIdx.z * sA + (size_t)(blockIdx.y * 128) * K;
    const float* Bb = B + blockIdx.z * sB + (size_t)(blockIdx.x * 128) * K;
    float* Cb = C + blockIdx.z * sC;
    int m0 = blockIdx.y * 128, n0 = blockIdx.x * 128;

    int tid  = threadIdx.x;
    int lane = tid & 31;
    int warp = tid >> 5;
    int wm = (warp >> 2) * 64;    // warp m offset (0,64)
    int wn = (warp & 3) * 32;     // warp n offset (0,32,64,96)

    float acc[4][4][4] = {};      // [m-atom][n-atom][frag]

    // gmem tile load mapping: 128 rows x 32 k per operand, float4 per thread x4
    int lr = tid >> 3;            // 0..31 (row group)
    int lk = (tid & 7) * 4;       // k offset 0..28

    float4 pa[4], pb[4];
    #pragma unroll
    for (int it = 0; it < 4; it++) {
        pa[it] = *(const float4*)&Ab[(size_t)(lr + it * 32) * K + lk];
        pb[it] = *(const float4*)&Bb[(size_t)(lr + it * 32) * K + lk];
    }

    for (int k0 = 0; k0 < K; k0 += 32) {
        // regs -> smem (convert to tf32)
        #pragma unroll
        for (int it = 0; it < 4; it++) {
            uint32_t* a = &As[(lr + it * 32) * LDK + lk];
            a[0] = f2tf32(pa[it].x); a[1] = f2tf32(pa[it].y);
            a[2] = f2tf32(pa[it].z); a[3] = f2tf32(pa[it].w);
            uint32_t* b = &Bs[(lr + it * 32) * LDK + lk];
            b[0] = f2tf32(pb[it].x); b[1] = f2tf32(pb[it].y);
            b[2] = f2tf32(pb[it].z); b[3] = f2tf32(pb[it].w);
        }
        __syncthreads();

        // prefetch next k-tile
        if (k0 + 32 < K) {
            #pragma unroll
            for (int it = 0; it < 4; it++) {
                pa[it] = *(const float4*)&Ab[(size_t)(lr + it * 32) * K + k0 + 32 + lk];
                pb[it] = *(const float4*)&Bb[(size_t)(lr + it * 32) * K + k0 + 32 + lk];
            }
        }

        int r = lane >> 2, c = lane & 3;
        #pragma unroll
        for (int kk = 0; kk < 32; kk += 8) {
            uint32_t af[4][4], bf[4][2];
            #pragma unroll
            for (int ma = 0; ma < 4; ma++) {
                int row = wm + ma * 16;
                af[ma][0] = As[(row + r)     * LDK + kk + c];
                af[ma][1] = As[(row + r + 8) * LDK + kk + c];
                af[ma][2] = As[(row + r)     * LDK + kk + c + 4];
                af[ma][3] = As[(row + r + 8) * LDK + kk + c + 4];
            }
            #pragma unroll
            for (int na = 0; na < 4; na++) {
                int col = wn + na * 8;
                bf[na][0] = Bs[(col + r) * LDK + kk + c];       // b0: k=lane%4, n=lane/4
                bf[na][1] = Bs[(col + r) * LDK + kk + c + 4];   // b1: k=lane%4+4
            }
            #pragma unroll
            for (int ma = 0; ma < 4; ma++)
                #pragma unroll
                for (int na = 0; na < 4; na++)
                    mma_tf32(acc[ma][na],
                             af[ma][0], af[ma][1], af[ma][2], af[ma][3],
                             bf[na][0], bf[na][1]);
        }
        __syncthreads();
    }

    // epilogue: c0 (r, 2c), c1 (r, 2c+1), c2 (r+8, 2c), c3 (r+8, 2c+1)
    int r = lane >> 2, cc = (lane & 3) * 2;
    #pragma unroll
    for (int ma = 0; ma < 4; ma++)
        #pragma unroll
        for (int na = 0; na < 4; na++) {
            int row = m0 + wm + ma * 16 + r;
            int col = n0 + wn + na * 8 + cc;
            float2 v0 = make_float2(acc[ma][na][0] * scale, acc[ma][na][1] * scale);
            float2 v1 = make_float2(acc[ma][na][2] * scale, acc[ma][na][3] * scale);
            *(float2*)&Cb[(size_t)row * N + col]       = v0;
            *(float2*)&Cb[(size_t)(row + 8) * N + col] = v1;
        }
}

// ---------------------------------------------------------------------------
// In-place row softmax over S
// ---------------------------------------------------------------------------
__global__ __launch_bounds__(256) void softmax_kernel()
{
    __shared__ float red[256];
    float* row = g_S + ((size_t)blockIdx.y * NN + blockIdx.x) * NN;
    int t = threadIdx.x;

    float vals[16];
    float m = -1e30f;
    #pragma unroll
    for (int u = 0; u < 16; u++) {
        vals[u] = row[t + u * 256];
        m = fmaxf(m, vals[u]);
    }
    red[t] = m;
    __syncthreads();
    for (int s = 128; s > 0; s >>= 1) {
        if (t < s) red[t] = fmaxf(red[t], red[t + s]);
        __syncthreads();
    }
    m = red[0];
    __syncthreads();

    float sum = 0.f;
    #pragma unroll
    for (int u = 0; u < 16; u++) {
        vals[u] = __expf(vals[u] - m);
        sum += vals[u];
    }
    red[t] = sum;
    __syncthreads();
    for (int s = 128; s > 0; s >>= 1) {
        if (t < s) red[t] += red[t + s];
        __syncthreads();
    }
    float inv = 1.0f / red[0];
    #pragma unroll
    for (int u = 0; u < 16; u++)
        row[t + u * 256] = vals[u] * inv;
}

// ---------------------------------------------------------------------------
// scores_out[b][j] = sum_i S[b][i][j], split over i with atomics
// ---------------------------------------------------------------------------
__global__ __launch_bounds__(256) void zero_scores(float* __restrict__ scores_out)
{
    int idx = blockIdx.x * 256 + threadIdx.x;
    if (idx < BB * NN) scores_out[idx] = 0.f;
}

__global__ __launch_bounds__(256) void colsum_kernel(float* __restrict__ scores_out)
{
    int b = blockIdx.z;
    int j = blockIdx.x * 256 + threadIdx.x;
    int i0 = blockIdx.y * 256;
    const float* Sb = g_S + (size_t)b * NN * NN;
    float s = 0.f;
    #pragma unroll 8
    for (int i = i0; i < i0 + 256; i++)
        s += Sb[(size_t)i * NN + j];
    atomicAdd(&scores_out[(size_t)b * NN + j], s);
}

// ---------------------------------------------------------------------------
extern "C" void kernel_launch(void* const* d_in, const int* in_sizes, int n_in,
                              void* d_out, int out_size)
{
    const float* x  = (const float*)d_in[0];
    const float* Wk = (const float*)d_in[1];
    const float* Wq = (const float*)d_in[2];
    const float* Wv = (const float*)d_in[3];

    float* out        = (float*)d_out;                 // (B, D, H, W) = [b][d][t]
    float* scores_out = out + (size_t)BB * DD * NN;    // (B, 1, H, W)

    float *Xt, *Q, *K, *Vt, *S;
    cudaGetSymbolAddress((void**)&Xt, g_Xt);
    cudaGetSymbolAddress((void**)&Q,  g_Q);
    cudaGetSymbolAddress((void**)&K,  g_K);
    cudaGetSymbolAddress((void**)&Vt, g_Vt);
    cudaGetSymbolAddress((void**)&S,  g_S);

    // 1) transpose x -> Xt[b][t][c]
    transpose_x<<<dim3(NN / 32, CC / 32, BB), dim3(32, 8)>>>(x, Xt);

    // 2) Q[t][d] = Xt . Wq^T   (M=N tokens, N=DD, K=CC)
    gemm_tc<<<dim3(DD / 128, NN / 128, BB), 256>>>(
        Xt, Wq, Q, NN, DD, CC,
        (size_t)NN * CC, 0, (size_t)NN * DD, 1.0f);
    // 3) K[t][d] = Xt . Wk^T
    gemm_tc<<<dim3(DD / 128, NN / 128, BB), 256>>>(
        Xt, Wk, K, NN, DD, CC,
        (size_t)NN * CC, 0, (size_t)NN * DD, 1.0f);
    // 4) Vt[d][t] = Wv . Xt^T   (operands swapped -> transposed V for free)
    gemm_tc<<<dim3(NN / 128, DD / 128, BB), 256>>>(
        Wv, Xt, Vt, DD, NN, CC,
        0, (size_t)NN * CC, (size_t)DD * NN, 1.0f);

    // 5) S[i][j] = SCALE * Q . K^T
    gemm_tc<<<dim3(NN / 128, NN / 128, BB), 256>>>(
        Q, K, S, NN, NN, DD,
        (size_t)NN * DD, (size_t)NN * DD, (size_t)NN * NN, SCALE);

    // 6) softmax rows of S in place
    softmax_kernel<<<dim3(NN, BB), 256>>>();

    // 7) out[d][t] = Vt . S^T  (K = tokens j)
    gemm_tc<<<dim3(NN / 128, DD / 128, BB), 256>>>(
        Vt, S, out, DD, NN, NN,
        (size_t)DD * NN, (size_t)NN * NN, (size_t)DD * NN, 1.0f);

    // 8) scores_out[b][j] = sum_i S[b][i][j]
    zero_scores<<<(BB * NN + 255) / 256, 256>>>(scores_out);
    colsum_kernel<<<dim3(NN / 256, NN / 256, BB), 256>>>(scores_out);
}

// round 6
// speedup vs baseline: 1.0537x; 1.0532x over previous
#include <cuda_runtime.h>
#include <math.h>
#include <stdint.h>

#define BB 4
#define CC 512
#define NN 4096   // H*W
#define DD 512
#define SCALE 0.04419417382415922f   // 1/sqrt(512)

// Scratch (__device__ globals; no allocation allowed)
__device__ float g_Xt[(size_t)BB * NN * CC];     // x transposed: [b][t][c]
__device__ float g_Q [(size_t)BB * NN * DD];     // [b][t][d]
__device__ float g_K [(size_t)BB * NN * DD];     // [b][t][d]
__device__ float g_Vt[(size_t)BB * DD * NN];     // [b][d][t]  (V transposed)
__device__ float g_S [(size_t)BB * NN * NN];     // [b][i][j]

// ---------------------------------------------------------------------------
__device__ __forceinline__ uint32_t f2tf32(float x) {
    uint32_t r;
    asm("cvt.rna.tf32.f32 %0, %1;\n" : "=r"(r) : "f"(x));
    return r;
}

__device__ __forceinline__ void mma_tf32(float c[4],
    uint32_t a0, uint32_t a1, uint32_t a2, uint32_t a3,
    uint32_t b0, uint32_t b1)
{
    asm volatile(
        "mma.sync.aligned.m16n8k8.row.col.f32.tf32.tf32.f32 "
        "{%0,%1,%2,%3}, {%4,%5,%6,%7}, {%8,%9}, {%0,%1,%2,%3};\n"
        : "+f"(c[0]), "+f"(c[1]), "+f"(c[2]), "+f"(c[3])
        : "r"(a0), "r"(a1), "r"(a2), "r"(a3), "r"(b0), "r"(b1));
}

// ---------------------------------------------------------------------------
// x (B,C,N) -> Xt (B,N,C)
// ---------------------------------------------------------------------------
__global__ __launch_bounds__(256) void transpose_x(const float* __restrict__ x,
                                                   float* __restrict__ xt)
{
    __shared__ float tile[32][33];
    int b  = blockIdx.z;
    int t0 = blockIdx.x * 32;
    int c0 = blockIdx.y * 32;
    const float* in = x + (size_t)b * CC * NN;
    float* out = xt + (size_t)b * NN * CC;

    #pragma unroll
    for (int i = threadIdx.y; i < 32; i += 8)
        tile[i][threadIdx.x] = in[(size_t)(c0 + i) * NN + t0 + threadIdx.x];
    __syncthreads();
    #pragma unroll
    for (int i = threadIdx.y; i < 32; i += 8)
        out[(size_t)(t0 + i) * CC + c0 + threadIdx.x] = tile[threadIdx.x][i];
}

// ---------------------------------------------------------------------------
// tf32 GEMM:  C[m][n] = scale * sum_k A[m][k] * B[n][k]
// Block tile 128(m) x 64(n), k-tile 32. 256 threads, 8 warps (4m x 2n),
// warp tile 32x32 of m16n8k8 atoms. Double-buffered smem (one sync/k-tile),
// STS.128 conflict-free stores, 2 CTAs/SM.
// ---------------------------------------------------------------------------
#define LDK 36                      // padded stride: (4r+c)%32 distinct -> LDS conflict-free
#define SBUF ((128 + 64) * LDK)     // words per stage

__global__ __launch_bounds__(256, 2) void gemm_tc(
    const float* __restrict__ A, const float* __restrict__ B, float* __restrict__ C,
    int N, int K,
    size_t sA, size_t sB, size_t sC, float scale)
{
    extern __shared__ uint32_t smem[];   // 2 * SBUF words

    const float* Ab = A + blockIdx.z * sA + (size_t)(blockIdx.y * 128) * K;
    const float* Bb = B + blockIdx.z * sB + (size_t)(blockIdx.x * 64) * K;
    float* Cb = C + blockIdx.z * sC;
    int m0 = blockIdx.y * 128, n0 = blockIdx.x * 64;

    int tid  = threadIdx.x;
    int lane = tid & 31;
    int warp = tid >> 5;
    int wm = (warp >> 1) * 32;    // 0,32,64,96
    int wn = (warp & 1) * 32;     // 0,32

    float acc[2][4][4] = {};      // [m-atom][n-atom][frag]

    int lr = tid >> 3;            // 0..31
    int lk = (tid & 7) * 4;       // 0..28

    float4 pa[4], pb[2];
    #pragma unroll
    for (int it = 0; it < 4; it++)
        pa[it] = *(const float4*)&Ab[(size_t)(lr + it * 32) * K + lk];
    #pragma unroll
    for (int it = 0; it < 2; it++)
        pb[it] = *(const float4*)&Bb[(size_t)(lr + it * 32) * K + lk];

    // store stage 0
    {
        uint32_t* As = smem;
        uint32_t* Bs = smem + 128 * LDK;
        #pragma unroll
        for (int it = 0; it < 4; it++) {
            uint4 v = make_uint4(f2tf32(pa[it].x), f2tf32(pa[it].y),
                                 f2tf32(pa[it].z), f2tf32(pa[it].w));
            *(uint4*)&As[(lr + it * 32) * LDK + lk] = v;
        }
        #pragma unroll
        for (int it = 0; it < 2; it++) {
            uint4 v = make_uint4(f2tf32(pb[it].x), f2tf32(pb[it].y),
                                 f2tf32(pb[it].z), f2tf32(pb[it].w));
            *(uint4*)&Bs[(lr + it * 32) * LDK + lk] = v;
        }
    }
    __syncthreads();

    int nk = K >> 5;
    int r = lane >> 2, c = lane & 3;

    for (int kt = 0; kt < nk; kt++) {
        int p = kt & 1;
        bool more = (kt + 1 < nk);

        // prefetch next k-tile into regs (overlaps the MMA loop below)
        if (more) {
            int ko = (kt + 1) * 32;
            #pragma unroll
            for (int it = 0; it < 4; it++)
                pa[it] = *(const float4*)&Ab[(size_t)(lr + it * 32) * K + ko + lk];
            #pragma unroll
            for (int it = 0; it < 2; it++)
                pb[it] = *(const float4*)&Bb[(size_t)(lr + it * 32) * K + ko + lk];
        }

        // compute on stage p
        {
            const uint32_t* As = smem + p * SBUF;
            const uint32_t* Bs = As + 128 * LDK;
            #pragma unroll
            for (int kk = 0; kk < 32; kk += 8) {
                uint32_t af[2][4], bf[4][2];
                #pragma unroll
                for (int ma = 0; ma < 2; ma++) {
                    int row = wm + ma * 16;
                    af[ma][0] = As[(row + r)     * LDK + kk + c];
                    af[ma][1] = As[(row + r + 8) * LDK + kk + c];
                    af[ma][2] = As[(row + r)     * LDK + kk + c + 4];
                    af[ma][3] = As[(row + r + 8) * LDK + kk + c + 4];
                }
                #pragma unroll
                for (int na = 0; na < 4; na++) {
                    int col = wn + na * 8;
                    bf[na][0] = Bs[(col + r) * LDK + kk + c];
                    bf[na][1] = Bs[(col + r) * LDK + kk + c + 4];
                }
                #pragma unroll
                for (int ma = 0; ma < 2; ma++)
                    #pragma unroll
                    for (int na = 0; na < 4; na++)
                        mma_tf32(acc[ma][na],
                                 af[ma][0], af[ma][1], af[ma][2], af[ma][3],
                                 bf[na][0], bf[na][1]);
            }
        }

        // store next tile into the other stage (no sync needed before:
        // stage 1-p was last read in iteration kt-1, protected by its sync)
        if (more) {
            uint32_t* As = smem + (1 - p) * SBUF;
            uint32_t* Bs = As + 128 * LDK;
            #pragma unroll
            for (int it = 0; it < 4; it++) {
                uint4 v = make_uint4(f2tf32(pa[it].x), f2tf32(pa[it].y),
                                     f2tf32(pa[it].z), f2tf32(pa[it].w));
                *(uint4*)&As[(lr + it * 32) * LDK + lk] = v;
            }
            #pragma unroll
            for (int it = 0; it < 2; it++) {
                uint4 v = make_uint4(f2tf32(pb[it].x), f2tf32(pb[it].y),
                                     f2tf32(pb[it].z), f2tf32(pb[it].w));
                *(uint4*)&Bs[(lr + it * 32) * LDK + lk] = v;
            }
            __syncthreads();
        }
    }

    // epilogue
    int cc = (lane & 3) * 2;
    #pragma unroll
    for (int ma = 0; ma < 2; ma++)
        #pragma unroll
        for (int na = 0; na < 4; na++) {
            int row = m0 + wm + ma * 16 + r;
            int col = n0 + wn + na * 8 + cc;
            float2 v0 = make_float2(acc[ma][na][0] * scale, acc[ma][na][1] * scale);
            float2 v1 = make_float2(acc[ma][na][2] * scale, acc[ma][na][3] * scale);
            *(float2*)&Cb[(size_t)row * N + col]       = v0;
            *(float2*)&Cb[(size_t)(row + 8) * N + col] = v1;
        }
}

// ---------------------------------------------------------------------------
// In-place row softmax over S
// ---------------------------------------------------------------------------
__global__ __launch_bounds__(256) void softmax_kernel()
{
    __shared__ float red[256];
    float* row = g_S + ((size_t)blockIdx.y * NN + blockIdx.x) * NN;
    int t = threadIdx.x;

    float vals[16];
    float m = -1e30f;
    #pragma unroll
    for (int u = 0; u < 16; u++) {
        vals[u] = row[t + u * 256];
        m = fmaxf(m, vals[u]);
    }
    red[t] = m;
    __syncthreads();
    for (int s = 128; s > 0; s >>= 1) {
        if (t < s) red[t] = fmaxf(red[t], red[t + s]);
        __syncthreads();
    }
    m = red[0];
    __syncthreads();

    float sum = 0.f;
    #pragma unroll
    for (int u = 0; u < 16; u++) {
        vals[u] = __expf(vals[u] - m);
        sum += vals[u];
    }
    red[t] = sum;
    __syncthreads();
    for (int s = 128; s > 0; s >>= 1) {
        if (t < s) red[t] += red[t + s];
        __syncthreads();
    }
    float inv = 1.0f / red[0];
    #pragma unroll
    for (int u = 0; u < 16; u++)
        row[t + u * 256] = vals[u] * inv;
}

// ---------------------------------------------------------------------------
// scores_out[b][j] = sum_i S[b][i][j], split over i with atomics
// ---------------------------------------------------------------------------
__global__ __launch_bounds__(256) void zero_scores(float* __restrict__ scores_out)
{
    int idx = blockIdx.x * 256 + threadIdx.x;
    if (idx < BB * NN) scores_out[idx] = 0.f;
}

__global__ __launch_bounds__(256) void colsum_kernel(float* __restrict__ scores_out)
{
    int b = blockIdx.z;
    int j = blockIdx.x * 256 + threadIdx.x;
    int i0 = blockIdx.y * 256;
    const float* Sb = g_S + (size_t)b * NN * NN;
    float s = 0.f;
    #pragma unroll 8
    for (int i = i0; i < i0 + 256; i++)
        s += Sb[(size_t)i * NN + j];
    atomicAdd(&scores_out[(size_t)b * NN + j], s);
}

// ---------------------------------------------------------------------------
extern "C" void kernel_launch(void* const* d_in, const int* in_sizes, int n_in,
                              void* d_out, int out_size)
{
    const float* x  = (const float*)d_in[0];
    const float* Wk = (const float*)d_in[1];
    const float* Wq = (const float*)d_in[2];
    const float* Wv = (const float*)d_in[3];

    float* out        = (float*)d_out;                 // (B, D, H, W) = [b][d][t]
    float* scores_out = out + (size_t)BB * DD * NN;    // (B, 1, H, W)

    float *Xt, *Q, *K, *Vt, *S;
    cudaGetSymbolAddress((void**)&Xt, g_Xt);
    cudaGetSymbolAddress((void**)&Q,  g_Q);
    cudaGetSymbolAddress((void**)&K,  g_K);
    cudaGetSymbolAddress((void**)&Vt, g_Vt);
    cudaGetSymbolAddress((void**)&S,  g_S);

    const int SMEM = 2 * SBUF * 4;   // 55296 bytes
    cudaFuncSetAttribute(gemm_tc, cudaFuncAttributeMaxDynamicSharedMemorySize, SMEM);

    // 1) transpose x -> Xt[b][t][c]
    transpose_x<<<dim3(NN / 32, CC / 32, BB), dim3(32, 8)>>>(x, Xt);

    // 2) Q[t][d] = Xt . Wq^T
    gemm_tc<<<dim3(DD / 64, NN / 128, BB), 256, SMEM>>>(
        Xt, Wq, Q, DD, CC, (size_t)NN * CC, 0, (size_t)NN * DD, 1.0f);
    // 3) K[t][d] = Xt . Wk^T
    gemm_tc<<<dim3(DD / 64, NN / 128, BB), 256, SMEM>>>(
        Xt, Wk, K, DD, CC, (size_t)NN * CC, 0, (size_t)NN * DD, 1.0f);
    // 4) Vt[d][t] = Wv . Xt^T
    gemm_tc<<<dim3(NN / 64, DD / 128, BB), 256, SMEM>>>(
        Wv, Xt, Vt, NN, CC, 0, (size_t)NN * CC, (size_t)DD * NN, 1.0f);

    // 5) S[i][j] = SCALE * Q . K^T
    gemm_tc<<<dim3(NN / 64, NN / 128, BB), 256, SMEM>>>(
        Q, K, S, NN, DD, (size_t)NN * DD, (size_t)NN * DD, (size_t)NN * NN, SCALE);

    // 6) softmax rows of S in place
    softmax_kernel<<<dim3(NN, BB), 256>>>();

    // 7) out[d][t] = Vt . S^T
    gemm_tc<<<dim3(NN / 64, DD / 128, BB), 256, SMEM>>>(
        Vt, S, out, NN, NN, (size_t)DD * NN, (size_t)NN * NN, (size_t)DD * NN, 1.0f);

    // 8) scores_out[b][j] = sum_i S[b][i][j]
    zero_scores<<<(BB * NN + 255) / 256, 256>>>(scores_out);
    colsum_kernel<<<dim3(NN / 256, NN / 256, BB), 256>>>(scores_out);
}

// round 8
// speedup vs baseline: 2.0171x; 1.9143x over previous
#include <cuda_runtime.h>
#include <cuda_fp16.h>
#include <stdint.h>

#define BB 4
#define CC 512
#define NN 4096   // H*W
#define DD 512
#define SCALE 0.04419417382415922f   // 1/sqrt(512)

// Scratch (__device__ globals; no allocation allowed)
__device__ __half g_Xth[(size_t)BB * NN * CC];   // x transposed, fp16: [b][t][c]
__device__ __half g_Qh [(size_t)BB * NN * DD];   // [b][t][d]
__device__ __half g_Kh [(size_t)BB * NN * DD];   // [b][t][d]
__device__ __half g_Vth[(size_t)BB * DD * NN];   // [b][d][t] (V transposed)
__device__ __half g_Wqh[(size_t)DD * CC];
__device__ __half g_Wkh[(size_t)DD * CC];
__device__ __half g_Wvh[(size_t)DD * CC];
__device__ float  g_S  [(size_t)BB * NN * NN];   // f32 scores (pre/post softmax input)
__device__ __half g_Sh [(size_t)BB * NN * NN];   // fp16 probs for O GEMM

// ---------------------------------------------------------------------------
__device__ __forceinline__ uint32_t smem_u32(const void* p) {
    uint32_t a;
    asm("{ .reg .u64 t; cvta.to.shared.u64 t, %1; cvt.u32.u64 %0, t; }"
        : "=r"(a) : "l"(p));
    return a;
}

__device__ __forceinline__ void mma_f16(float c[4],
    uint32_t a0, uint32_t a1, uint32_t a2, uint32_t a3,
    uint32_t b0, uint32_t b1)
{
    asm volatile(
        "mma.sync.aligned.m16n8k16.row.col.f32.f16.f16.f32 "
        "{%0,%1,%2,%3}, {%4,%5,%6,%7}, {%8,%9}, {%0,%1,%2,%3};\n"
        : "+f"(c[0]), "+f"(c[1]), "+f"(c[2]), "+f"(c[3])
        : "r"(a0), "r"(a1), "r"(a2), "r"(a3), "r"(b0), "r"(b1));
}

// ---------------------------------------------------------------------------
// fp16 GEMM: C[m][n] = scale * sum_k A[m][k] * B[n][k]   (A,B fp16; acc fp32)
// CTA tile 128x128, k-tile 32, 8 warps (2m x 4n), warp tile 64x32.
// 3-stage cp.async pipeline, one __syncthreads per k-tile, 2 CTAs/SM.
// Smem row stride 40 halfs (80B): row step = 20 words == 4 (mod 32) banks
// -> all fragment LDS.32 conflict-free.
// ---------------------------------------------------------------------------
#define TM 128
#define TN 128
#define KT 32
#define NST 3
#define ROWB 80                         // bytes per smem row (40 halfs)
#define A_BYTES (TM * ROWB)             // 10240
#define STAGE   (2 * A_BYTES)           // 20480 (A + B)
#define GSMEM   (NST * STAGE)           // 61440

__device__ __forceinline__ void load_tile(uint32_t sst, const __half* __restrict__ Ab,
                                          const __half* __restrict__ Bb,
                                          int K, int ko, int tid)
{
    #pragma unroll
    for (int j = 0; j < 2; j++) {       // A: 128 rows x 4 uint4
        int i = tid + j * 256, row = i >> 2, q = i & 3;
        uint32_t dst = sst + row * ROWB + q * 16;
        const __half* src = Ab + (size_t)row * K + ko + q * 8;
        asm volatile("cp.async.cg.shared.global [%0], [%1], 16;\n" :: "r"(dst), "l"(src));
    }
    #pragma unroll
    for (int j = 0; j < 2; j++) {       // B: 128 rows x 4 uint4
        int i = tid + j * 256, row = i >> 2, q = i & 3;
        uint32_t dst = sst + A_BYTES + row * ROWB + q * 16;
        const __half* src = Bb + (size_t)row * K + ko + q * 8;
        asm volatile("cp.async.cg.shared.global [%0], [%1], 16;\n" :: "r"(dst), "l"(src));
    }
    asm volatile("cp.async.commit_group;\n");
}

template <bool HALF_OUT>
__global__ __launch_bounds__(256, 2) void gemm_h(
    const __half* __restrict__ A, const __half* __restrict__ B, void* __restrict__ Cv,
    int Nglob, int K, size_t sA, size_t sB, size_t sC, float scale)
{
    extern __shared__ char sm[];
    uint32_t sbase = smem_u32(sm);
    int tid = threadIdx.x, lane = tid & 31, warp = tid >> 5;
    int r = lane >> 2, c = lane & 3;
    int wm = (warp >> 2) * 64;          // 0,64
    int wn = (warp & 3) * 32;           // 0,32,64,96

    const __half* Ab = A + blockIdx.z * sA + (size_t)(blockIdx.y * TM) * K;
    const __half* Bb = B + blockIdx.z * sB + (size_t)(blockIdx.x * TN) * K;
    int m0 = blockIdx.y * TM, n0 = blockIdx.x * TN;

    float acc[4][4][4] = {};            // [m-atom][n-atom][frag]

    int nk = K / KT;
    // prologue: 2 stages in flight
    load_tile(sbase + 0 * STAGE, Ab, Bb, K, 0, tid);
    load_tile(sbase + 1 * STAGE, Ab, Bb, K, KT, tid);

    for (int kt = 0; kt < nk; kt++) {
        if (kt < nk - 1) asm volatile("cp.async.wait_group 1;\n" ::: "memory");
        else             asm volatile("cp.async.wait_group 0;\n" ::: "memory");
        __syncthreads();

        if (kt + 2 < nk)
            load_tile(sbase + ((kt + 2) % NST) * STAGE, Ab, Bb, K, (kt + 2) * KT, tid);

        const char* As = sm + (kt % NST) * STAGE;
        const char* Bs = As + A_BYTES;

        #pragma unroll
        for (int kk = 0; kk < 2; kk++) {
            uint32_t af[2][4], bf[4][2];
            #pragma unroll
            for (int ma = 0; ma < 2; ma++) {
                int row = wm + ma * 16 + r;
                const char* p = As + row * ROWB + kk * 32 + c * 4;
                af[ma][0] = *(const uint32_t*)(p);
                af[ma][1] = *(const uint32_t*)(p + 8 * ROWB);
                af[ma][2] = *(const uint32_t*)(p + 16);
                af[ma][3] = *(const uint32_t*)(p + 8 * ROWB + 16);
            }
            #pragma unroll
            for (int na = 0; na < 4; na++) {
                int col = wn + na * 8 + r;
                const char* p = Bs + col * ROWB + kk * 32 + c * 4;
                bf[na][0] = *(const uint32_t*)(p);
                bf[na][1] = *(const uint32_t*)(p + 16);
            }
            #pragma unroll
            for (int ma = 0; ma < 2; ma++)
                #pragma unroll
                for (int na = 0; na < 4; na++)
                    mma_f16(acc[ma * 2 + kk == -1 ? 0 : ma][na],  // placeholder (fixed below)
                            af[ma][0], af[ma][1], af[ma][2], af[ma][3],
                            bf[na][0], bf[na][1]);
        }
    }

    // epilogue
    int cc = c * 2;
    #pragma unroll
    for (int ma = 0; ma < 2; ma++)
        #pragma unroll
        for (int na = 0; na < 4; na++) {
            int row = m0 + wm + ma * 16 + r;
            int col = n0 + wn + na * 8 + cc;
            float v0 = acc[ma][na][0] * scale, v1 = acc[ma][na][1] * scale;
            float v2 = acc[ma][na][2] * scale, v3 = acc[ma][na][3] * scale;
            if (HALF_OUT) {
                __half* Cb = (__half*)Cv + blockIdx.z * sC;
                *(__half2*)&Cb[(size_t)row * Nglob + col]       = __floats2half2_rn(v0, v1);
                *(__half2*)&Cb[(size_t)(row + 8) * Nglob + col] = __floats2half2_rn(v2, v3);
            } else {
                float* Cb = (float*)Cv + blockIdx.z * sC;
                *(float2*)&Cb[(size_t)row * Nglob + col]       = make_float2(v0, v1);
                *(float2*)&Cb[(size_t)(row + 8) * Nglob + col] = make_float2(v2, v3);
            }
        }
}

// NOTE on the warp tile: wm spans 64 rows = 4 m-atoms, but af/acc above use 2.
// The "2" is the m-atom pair within the kk loop? No — fix: m-atoms must be 4.
// (Corrected implementation below replaces the buggy placeholder line.)

// ---------------------------------------------------------------------------
// x (B,C,N) f32 -> Xt (B,N,C) fp16
// ---------------------------------------------------------------------------
__global__ __launch_bounds__(256) void transpose_x(const float* __restrict__ x)
{
    __shared__ float tile[32][33];
    int b  = blockIdx.z;
    int t0 = blockIdx.x * 32;
    int c0 = blockIdx.y * 32;
    const float* in = x + (size_t)b * CC * NN;
    __half* out = g_Xth + (size_t)b * NN * CC;

    #pragma unroll
    for (int i = threadIdx.y; i < 32; i += 8)
        tile[i][threadIdx.x] = in[(size_t)(c0 + i) * NN + t0 + threadIdx.x];
    __syncthreads();
    #pragma unroll
    for (int i = threadIdx.y; i < 32; i += 8)
        out[(size_t)(t0 + i) * CC + c0 + threadIdx.x] = __float2half_rn(tile[threadIdx.x][i]);
}

__global__ __launch_bounds__(256) void conv_w(const float* __restrict__ Wq,
                                              const float* __restrict__ Wk,
                                              const float* __restrict__ Wv)
{
    int i = blockIdx.x * 256 + threadIdx.x;
    if (i < DD * CC) {
        g_Wqh[i] = __float2half_rn(Wq[i]);
        g_Wkh[i] = __float2half_rn(Wk[i]);
        g_Wvh[i] = __float2half_rn(Wv[i]);
    }
}

// ---------------------------------------------------------------------------
// Row softmax: read f32 S, write fp16 probs to g_Sh
// ---------------------------------------------------------------------------
__global__ __launch_bounds__(256) void softmax_kernel()
{
    __shared__ float red[256];
    size_t base = ((size_t)blockIdx.y * NN + blockIdx.x) * NN;
    const float* row = g_S + base;
    __half* rowh = g_Sh + base;
    int t = threadIdx.x;

    float vals[16];
    float m = -1e30f;
    #pragma unroll
    for (int u = 0; u < 16; u++) {
        vals[u] = row[t + u * 256];
        m = fmaxf(m, vals[u]);
    }
    red[t] = m;
    __syncthreads();
    for (int s = 128; s > 0; s >>= 1) {
        if (t < s) red[t] = fmaxf(red[t], red[t + s]);
        __syncthreads();
    }
    m = red[0];
    __syncthreads();

    float sum = 0.f;
    #pragma unroll
    for (int u = 0; u < 16; u++) {
        vals[u] = __expf(vals[u] - m);
        sum += vals[u];
    }
    red[t] = sum;
    __syncthreads();
    for (int s = 128; s > 0; s >>= 1) {
        if (t < s) red[t] += red[t + s];
        __syncthreads();
    }
    float inv = 1.0f / red[0];
    #pragma unroll
    for (int u = 0; u < 16; u++)
        rowh[t + u * 256] = __float2half_rn(vals[u] * inv);
}

// ---------------------------------------------------------------------------
// scores_out[b][j] = sum_i P[b][i][j] from fp16 probs
// ---------------------------------------------------------------------------
__global__ __launch_bounds__(256) void zero_scores(float* __restrict__ scores_out)
{
    int idx = blockIdx.x * 256 + threadIdx.x;
    if (idx < BB * NN) scores_out[idx] = 0.f;
}

__global__ __launch_bounds__(256) void colsum_kernel(float* __restrict__ scores_out)
{
    int b = blockIdx.z;
    int j = blockIdx.x * 256 + threadIdx.x;
    int i0 = blockIdx.y * 256;
    const __half* Sb = g_Sh + (size_t)b * NN * NN;
    float s = 0.f;
    #pragma unroll 8
    for (int i = i0; i < i0 + 256; i++)
        s += __half2float(Sb[(size_t)i * NN + j]);
    atomicAdd(&scores_out[(size_t)b * NN + j], s);
}

// ---------------------------------------------------------------------------
// Corrected GEMM (4 m-atoms): defined here to supersede the sketch above.
// ---------------------------------------------------------------------------
template <bool HALF_OUT>
__global__ __launch_bounds__(256, 2) void gemm_h2(
    const __half* __restrict__ A, const __half* __restrict__ B, void* __restrict__ Cv,
    int Nglob, int K, size_t sA, size_t sB, size_t sC, float scale)
{
    extern __shared__ char sm[];
    uint32_t sbase = smem_u32(sm);
    int tid = threadIdx.x, lane = tid & 31, warp = tid >> 5;
    int r = lane >> 2, c = lane & 3;
    int wm = (warp >> 2) * 64;          // 0,64   (warp tile 64m x 32n)
    int wn = (warp & 3) * 32;           // 0,32,64,96

    const __half* Ab = A + blockIdx.z * sA + (size_t)(blockIdx.y * TM) * K;
    const __half* Bb = B + blockIdx.z * sB + (size_t)(blockIdx.x * TN) * K;
    int m0 = blockIdx.y * TM, n0 = blockIdx.x * TN;

    float acc[4][4][4] = {};            // [m-atom(16)][n-atom(8)][frag]

    int nk = K / KT;
    load_tile(sbase + 0 * STAGE, Ab, Bb, K, 0, tid);
    load_tile(sbase + 1 * STAGE, Ab, Bb, K, KT, tid);

    for (int kt = 0; kt < nk; kt++) {
        if (kt < nk - 1) asm volatile("cp.async.wait_group 1;\n" ::: "memory");
        else             asm volatile("cp.async.wait_group 0;\n" ::: "memory");
        __syncthreads();

        if (kt + 2 < nk)
            load_tile(sbase + ((kt + 2) % NST) * STAGE, Ab, Bb, K, (kt + 2) * KT, tid);

        const char* As = sm + (kt % NST) * STAGE;
        const char* Bs = As + A_BYTES;

        #pragma unroll
        for (int kk = 0; kk < 2; kk++) {
            uint32_t af[4][4], bf[4][2];
            #pragma unroll
            for (int ma = 0; ma < 4; ma++) {
                const char* p = As + (wm + ma * 16 + r) * ROWB + kk * 32 + c * 4;
                af[ma][0] = *(const uint32_t*)(p);
                af[ma][1] = *(const uint32_t*)(p + 8 * ROWB);
                af[ma][2] = *(const uint32_t*)(p + 16);
                af[ma][3] = *(const uint32_t*)(p + 8 * ROWB + 16);
            }
            #pragma unroll
            for (int na = 0; na < 4; na++) {
                const char* p = Bs + (wn + na * 8 + r) * ROWB + kk * 32 + c * 4;
                bf[na][0] = *(const uint32_t*)(p);
                bf[na][1] = *(const uint32_t*)(p + 16);
            }
            #pragma unroll
            for (int ma = 0; ma < 4; ma++)
                #pragma unroll
                for (int na = 0; na < 4; na++)
                    mma_f16(acc[ma][na],
                            af[ma][0], af[ma][1], af[ma][2], af[ma][3],
                            bf[na][0], bf[na][1]);
        }
    }

    int cc = c * 2;
    #pragma unroll
    for (int ma = 0; ma < 4; ma++)
        #pragma unroll
        for (int na = 0; na < 4; na++) {
            int row = m0 + wm + ma * 16 + r;
            int col = n0 + wn + na * 8 + cc;
            float v0 = acc[ma][na][0] * scale, v1 = acc[ma][na][1] * scale;
            float v2 = acc[ma][na][2] * scale, v3 = acc[ma][na][3] * scale;
            if (HALF_OUT) {
                __half* Cb = (__half*)Cv + blockIdx.z * sC;
                *(__half2*)&Cb[(size_t)row * Nglob + col]       = __floats2half2_rn(v0, v1);
                *(__half2*)&Cb[(size_t)(row + 8) * Nglob + col] = __floats2half2_rn(v2, v3);
            } else {
                float* Cb = (float*)Cv + blockIdx.z * sC;
                *(float2*)&Cb[(size_t)row * Nglob + col]       = make_float2(v0, v1);
                *(float2*)&Cb[(size_t)(row + 8) * Nglob + col] = make_float2(v2, v3);
            }
        }
}

// ---------------------------------------------------------------------------
extern "C" void kernel_launch(void* const* d_in, const int* in_sizes, int n_in,
                              void* d_out, int out_size)
{
    const float* x  = (const float*)d_in[0];
    const float* Wk = (const float*)d_in[1];
    const float* Wq = (const float*)d_in[2];
    const float* Wv = (const float*)d_in[3];

    float* out        = (float*)d_out;                 // (B, D, H, W) = [b][d][t]
    float* scores_out = out + (size_t)BB * DD * NN;    // (B, 1, H, W)

    __half *Xt, *Q, *K, *Vt, *Sh, *Wqh, *Wkh, *Wvh;
    float *S;
    cudaGetSymbolAddress((void**)&Xt,  g_Xth);
    cudaGetSymbolAddress((void**)&Q,   g_Qh);
    cudaGetSymbolAddress((void**)&K,   g_Kh);
    cudaGetSymbolAddress((void**)&Vt,  g_Vth);
    cudaGetSymbolAddress((void**)&S,   g_S);
    cudaGetSymbolAddress((void**)&Sh,  g_Sh);
    cudaGetSymbolAddress((void**)&Wqh, g_Wqh);
    cudaGetSymbolAddress((void**)&Wkh, g_Wkh);
    cudaGetSymbolAddress((void**)&Wvh, g_Wvh);

    cudaFuncSetAttribute(gemm_h2<true>,  cudaFuncAttributeMaxDynamicSharedMemorySize, GSMEM);
    cudaFuncSetAttribute(gemm_h2<false>, cudaFuncAttributeMaxDynamicSharedMemorySize, GSMEM);

    // 0) fp16 operand prep
    conv_w<<<(DD * CC + 255) / 256, 256>>>(Wq, Wk, Wv);
    transpose_x<<<dim3(NN / 32, CC / 32, BB), dim3(32, 8)>>>(x);

    // 1) Q[t][d] = Xt . Wq^T
    gemm_h2<true><<<dim3(DD / TN, NN / TM, BB), 256, GSMEM>>>(
        Xt, Wqh, Q, DD, CC, (size_t)NN * CC, 0, (size_t)NN * DD, 1.0f);
    // 2) K[t][d] = Xt . Wk^T
    gemm_h2<true><<<dim3(DD / TN, NN / TM, BB), 256, GSMEM>>>(
        Xt, Wkh, K, DD, CC, (size_t)NN * CC, 0, (size_t)NN * DD, 1.0f);
    // 3) Vt[d][t] = Wv . Xt^T
    gemm_h2<true><<<dim3(NN / TN, DD / TM, BB), 256, GSMEM>>>(
        Wvh, Xt, Vt, NN, CC, 0, (size_t)NN * CC, (size_t)DD * NN, 1.0f);

    // 4) S[i][j] = SCALE * Q . K^T   (f32 out)
    gemm_h2<false><<<dim3(NN / TN, NN / TM, BB), 256, GSMEM>>>(
        Q, K, S, NN, DD, (size_t)NN * DD, (size_t)NN * DD, (size_t)NN * NN, SCALE);

    // 5) softmax rows -> fp16 probs
    softmax_kernel<<<dim3(NN, BB), 256>>>();

    // 6) out[d][t] = Vt . P^T  (f32 out, d-major layout directly)
    gemm_h2<false><<<dim3(NN / TN, DD / TM, BB), 256, GSMEM>>>(
        Vt, Sh, out, NN, NN, (size_t)DD * NN, (size_t)NN * NN, (size_t)DD * NN, 1.0f);

    // 7) scores_out[b][j] = sum_i P[b][i][j]
    zero_scores<<<(BB * NN + 255) / 256, 256>>>(scores_out);
    colsum_kernel<<<dim3(NN / 256, NN / 256, BB), 256>>>(scores_out);
}

// round 9
// speedup vs baseline: 2.1819x; 1.0817x over previous
#include <cuda_runtime.h>
#include <cuda_fp16.h>
#include <stdint.h>

#define BB 4
#define CC 512
#define NN 4096   // H*W
#define DD 512
#define SCALE 0.04419417382415922f   // 1/sqrt(512)

// Scratch (__device__ globals; no allocation allowed)
__device__ __half g_Xth[(size_t)BB * NN * CC];   // x transposed, fp16: [b][t][c]
__device__ __half g_Qh [(size_t)BB * NN * DD];   // [b][t][d]
__device__ __half g_Kh [(size_t)BB * NN * DD];   // [b][t][d]
__device__ __half g_Vth[(size_t)BB * DD * NN];   // [b][d][t] (V transposed)
__device__ __half g_Wqh[(size_t)DD * CC];
__device__ __half g_Wkh[(size_t)DD * CC];
__device__ __half g_Wvh[(size_t)DD * CC];
__device__ float  g_S  [(size_t)BB * NN * NN];   // f32 scores
__device__ __half g_Sh [(size_t)BB * NN * NN];   // fp16 probs for O GEMM

// ---------------------------------------------------------------------------
__device__ __forceinline__ uint32_t smem_u32(const void* p) {
    uint32_t a;
    asm("{ .reg .u64 t; cvta.to.shared.u64 t, %1; cvt.u32.u64 %0, t; }"
        : "=r"(a) : "l"(p));
    return a;
}

__device__ __forceinline__ void mma_f16(float c[4],
    uint32_t a0, uint32_t a1, uint32_t a2, uint32_t a3,
    uint32_t b0, uint32_t b1)
{
    asm volatile(
        "mma.sync.aligned.m16n8k16.row.col.f32.f16.f16.f32 "
        "{%0,%1,%2,%3}, {%4,%5,%6,%7}, {%8,%9}, {%0,%1,%2,%3};\n"
        : "+f"(c[0]), "+f"(c[1]), "+f"(c[2]), "+f"(c[3])
        : "r"(a0), "r"(a1), "r"(a2), "r"(a3), "r"(b0), "r"(b1));
}

__device__ __forceinline__ void ldsm_x4(uint32_t& r0, uint32_t& r1,
                                        uint32_t& r2, uint32_t& r3, uint32_t addr)
{
    asm volatile("ldmatrix.sync.aligned.m8n8.x4.shared.b16 {%0,%1,%2,%3}, [%4];"
        : "=r"(r0), "=r"(r1), "=r"(r2), "=r"(r3) : "r"(addr));
}

// ---------------------------------------------------------------------------
// fp16 GEMM: C[m][n] = scale * sum_k A[m][k] * B[n][k]   (A,B fp16; acc fp32)
// CTA 128x128, k-tile 32, 8 warps (2m x 4n), warp tile 64x32.
// 4-stage cp.async pipeline (3 loads in flight), ldmatrix fragment loads.
// Smem row stride 80B: LDSM 8-row phases hit words {20r mod 32} = all banks.
// ---------------------------------------------------------------------------
#define TM 128
#define TN 128
#define KT 32
#define NST 4
#define ROWB 80                         // bytes per smem row (40 halfs)
#define A_BYTES (TM * ROWB)             // 10240
#define STAGE   (2 * A_BYTES)           // 20480 (A + B)
#define GSMEM   (NST * STAGE)           // 81920

__device__ __forceinline__ void load_tile(uint32_t sst, const __half* __restrict__ Ab,
                                          const __half* __restrict__ Bb,
                                          int K, int ko, int tid)
{
    #pragma unroll
    for (int j = 0; j < 2; j++) {       // A: 128 rows x 4 uint4
        int i = tid + j * 256, row = i >> 2, q = i & 3;
        uint32_t dst = sst + row * ROWB + q * 16;
        const __half* src = Ab + (size_t)row * K + ko + q * 8;
        asm volatile("cp.async.cg.shared.global [%0], [%1], 16;\n" :: "r"(dst), "l"(src));
    }
    #pragma unroll
    for (int j = 0; j < 2; j++) {       // B: 128 rows x 4 uint4
        int i = tid + j * 256, row = i >> 2, q = i & 3;
        uint32_t dst = sst + A_BYTES + row * ROWB + q * 16;
        const __half* src = Bb + (size_t)row * K + ko + q * 8;
        asm volatile("cp.async.cg.shared.global [%0], [%1], 16;\n" :: "r"(dst), "l"(src));
    }
    asm volatile("cp.async.commit_group;\n");
}

template <bool HALF_OUT>
__global__ __launch_bounds__(256, 2) void gemm_h2(
    const __half* __restrict__ A, const __half* __restrict__ B, void* __restrict__ Cv,
    int Nglob, int K, size_t sA, size_t sB, size_t sC, float scale)
{
    extern __shared__ char sm[];
    uint32_t sbase = smem_u32(sm);
    int tid = threadIdx.x, lane = tid & 31, warp = tid >> 5;
    int r = lane >> 2, c = lane & 3;
    int wm = (warp >> 2) * 64;          // 0,64   (warp tile 64m x 32n)
    int wn = (warp & 3) * 32;           // 0,32,64,96

    const __half* Ab = A + blockIdx.z * sA + (size_t)(blockIdx.y * TM) * K;
    const __half* Bb = B + blockIdx.z * sB + (size_t)(blockIdx.x * TN) * K;
    int m0 = blockIdx.y * TM, n0 = blockIdx.x * TN;

    float acc[4][4][4] = {};            // [m-atom][n-atom][frag]

    // ldmatrix per-lane address components (within a stage)
    uint32_t a_off = (uint32_t)(wm + (lane & 15)) * ROWB + (lane >> 4) * 16;
    uint32_t b_off = A_BYTES
                   + (uint32_t)(wn + ((lane >> 4) * 8) + (lane & 7)) * ROWB
                   + ((lane >> 3) & 1) * 16;

    int nk = K / KT;
    load_tile(sbase + 0 * STAGE, Ab, Bb, K, 0 * KT, tid);
    load_tile(sbase + 1 * STAGE, Ab, Bb, K, 1 * KT, tid);
    load_tile(sbase + 2 * STAGE, Ab, Bb, K, 2 * KT, tid);

    for (int kt = 0; kt < nk; kt++) {
        int rem = nk - 1 - kt;
        if (rem >= 2)      asm volatile("cp.async.wait_group 2;\n" ::: "memory");
        else if (rem == 1) asm volatile("cp.async.wait_group 1;\n" ::: "memory");
        else               asm volatile("cp.async.wait_group 0;\n" ::: "memory");
        __syncthreads();

        if (kt + 3 < nk)
            load_tile(sbase + ((kt + 3) % NST) * STAGE, Ab, Bb, K, (kt + 3) * KT, tid);

        uint32_t st = sbase + (kt % NST) * STAGE;

        #pragma unroll
        for (int kk = 0; kk < 2; kk++) {
            uint32_t af[4][4], bf[4][2];
            uint32_t ab = st + a_off + kk * 32;
            #pragma unroll
            for (int ma = 0; ma < 4; ma++)
                ldsm_x4(af[ma][0], af[ma][1], af[ma][2], af[ma][3],
                        ab + ma * 16 * ROWB);
            uint32_t bb = st + b_off + kk * 32;
            #pragma unroll
            for (int p = 0; p < 2; p++)
                ldsm_x4(bf[2 * p][0], bf[2 * p][1], bf[2 * p + 1][0], bf[2 * p + 1][1],
                        bb + p * 16 * ROWB);
            #pragma unroll
            for (int ma = 0; ma < 4; ma++)
                #pragma unroll
                for (int na = 0; na < 4; na++)
                    mma_f16(acc[ma][na],
                            af[ma][0], af[ma][1], af[ma][2], af[ma][3],
                            bf[na][0], bf[na][1]);
        }
    }

    int cc = c * 2;
    #pragma unroll
    for (int ma = 0; ma < 4; ma++)
        #pragma unroll
        for (int na = 0; na < 4; na++) {
            int row = m0 + wm + ma * 16 + r;
            int col = n0 + wn + na * 8 + cc;
            float v0 = acc[ma][na][0] * scale, v1 = acc[ma][na][1] * scale;
            float v2 = acc[ma][na][2] * scale, v3 = acc[ma][na][3] * scale;
            if (HALF_OUT) {
                __half* Cb = (__half*)Cv + blockIdx.z * sC;
                *(__half2*)&Cb[(size_t)row * Nglob + col]       = __floats2half2_rn(v0, v1);
                *(__half2*)&Cb[(size_t)(row + 8) * Nglob + col] = __floats2half2_rn(v2, v3);
            } else {
                float* Cb = (float*)Cv + blockIdx.z * sC;
                *(float2*)&Cb[(size_t)row * Nglob + col]       = make_float2(v0, v1);
                *(float2*)&Cb[(size_t)(row + 8) * Nglob + col] = make_float2(v2, v3);
            }
        }
}

// ---------------------------------------------------------------------------
// x (B,C,N) f32 -> Xt (B,N,C) fp16
// ---------------------------------------------------------------------------
__global__ __launch_bounds__(256) void transpose_x(const float* __restrict__ x)
{
    __shared__ float tile[32][33];
    int b  = blockIdx.z;
    int t0 = blockIdx.x * 32;
    int c0 = blockIdx.y * 32;
    const float* in = x + (size_t)b * CC * NN;
    __half* out = g_Xth + (size_t)b * NN * CC;

    #pragma unroll
    for (int i = threadIdx.y; i < 32; i += 8)
        tile[i][threadIdx.x] = in[(size_t)(c0 + i) * NN + t0 + threadIdx.x];
    __syncthreads();
    #pragma unroll
    for (int i = threadIdx.y; i < 32; i += 8)
        out[(size_t)(t0 + i) * CC + c0 + threadIdx.x] = __float2half_rn(tile[threadIdx.x][i]);
}

__global__ __launch_bounds__(256) void conv_w(const float* __restrict__ Wq,
                                              const float* __restrict__ Wk,
                                              const float* __restrict__ Wv)
{
    int i = blockIdx.x * 256 + threadIdx.x;
    if (i < DD * CC) {
        g_Wqh[i] = __float2half_rn(Wq[i]);
        g_Wkh[i] = __float2half_rn(Wk[i]);
        g_Wvh[i] = __float2half_rn(Wv[i]);
    }
}

// ---------------------------------------------------------------------------
// Row softmax: read f32 S, write fp16 probs to g_Sh
// ---------------------------------------------------------------------------
__global__ __launch_bounds__(256) void softmax_kernel()
{
    __shared__ float red[256];
    size_t base = ((size_t)blockIdx.y * NN + blockIdx.x) * NN;
    const float* row = g_S + base;
    __half* rowh = g_Sh + base;
    int t = threadIdx.x;

    float vals[16];
    float m = -1e30f;
    #pragma unroll
    for (int u = 0; u < 16; u++) {
        vals[u] = row[t + u * 256];
        m = fmaxf(m, vals[u]);
    }
    red[t] = m;
    __syncthreads();
    for (int s = 128; s > 0; s >>= 1) {
        if (t < s) red[t] = fmaxf(red[t], red[t + s]);
        __syncthreads();
    }
    m = red[0];
    __syncthreads();

    float sum = 0.f;
    #pragma unroll
    for (int u = 0; u < 16; u++) {
        vals[u] = __expf(vals[u] - m);
        sum += vals[u];
    }
    red[t] = sum;
    __syncthreads();
    for (int s = 128; s > 0; s >>= 1) {
        if (t < s) red[t] += red[t + s];
        __syncthreads();
    }
    float inv = 1.0f / red[0];
    #pragma unroll
    for (int u = 0; u < 16; u++)
        rowh[t + u * 256] = __float2half_rn(vals[u] * inv);
}

// ---------------------------------------------------------------------------
// scores_out[b][j] = sum_i P[b][i][j] from fp16 probs
// ---------------------------------------------------------------------------
__global__ __launch_bounds__(256) void zero_scores(float* __restrict__ scores_out)
{
    int idx = blockIdx.x * 256 + threadIdx.x;
    if (idx < BB * NN) scores_out[idx] = 0.f;
}

__global__ __launch_bounds__(256) void colsum_kernel(float* __restrict__ scores_out)
{
    int b = blockIdx.z;
    int j = blockIdx.x * 256 + threadIdx.x;
    int i0 = blockIdx.y * 256;
    const __half* Sb = g_Sh + (size_t)b * NN * NN;
    float s = 0.f;
    #pragma unroll 8
    for (int i = i0; i < i0 + 256; i++)
        s += __half2float(Sb[(size_t)i * NN + j]);
    atomicAdd(&scores_out[(size_t)b * NN + j], s);
}

// ---------------------------------------------------------------------------
extern "C" void kernel_launch(void* const* d_in, const int* in_sizes, int n_in,
                              void* d_out, int out_size)
{
    const float* x  = (const float*)d_in[0];
    const float* Wk = (const float*)d_in[1];
    const float* Wq = (const float*)d_in[2];
    const float* Wv = (const float*)d_in[3];

    float* out        = (float*)d_out;                 // (B, D, H, W) = [b][d][t]
    float* scores_out = out + (size_t)BB * DD * NN;    // (B, 1, H, W)

    __half *Xt, *Q, *K, *Vt, *Sh, *Wqh, *Wkh, *Wvh;
    float *S;
    cudaGetSymbolAddress((void**)&Xt,  g_Xth);
    cudaGetSymbolAddress((void**)&Q,   g_Qh);
    cudaGetSymbolAddress((void**)&K,   g_Kh);
    cudaGetSymbolAddress((void**)&Vt,  g_Vth);
    cudaGetSymbolAddress((void**)&S,   g_S);
    cudaGetSymbolAddress((void**)&Sh,  g_Sh);
    cudaGetSymbolAddress((void**)&Wqh, g_Wqh);
    cudaGetSymbolAddress((void**)&Wkh, g_Wkh);
    cudaGetSymbolAddress((void**)&Wvh, g_Wvh);

    cudaFuncSetAttribute(gemm_h2<true>,  cudaFuncAttributeMaxDynamicSharedMemorySize, GSMEM);
    cudaFuncSetAttribute(gemm_h2<false>, cudaFuncAttributeMaxDynamicSharedMemorySize, GSMEM);

    // 0) fp16 operand prep
    conv_w<<<(DD * CC + 255) / 256, 256>>>(Wq, Wk, Wv);
    transpose_x<<<dim3(NN / 32, CC / 32, BB), dim3(32, 8)>>>(x);

    // 1) Q[t][d] = Xt . Wq^T
    gemm_h2<true><<<dim3(DD / TN, NN / TM, BB), 256, GSMEM>>>(
        Xt, Wqh, Q, DD, CC, (size_t)NN * CC, 0, (size_t)NN * DD, 1.0f);
    // 2) K[t][d] = Xt . Wk^T
    gemm_h2<true><<<dim3(DD / TN, NN / TM, BB), 256, GSMEM>>>(
        Xt, Wkh, K, DD, CC, (size_t)NN * CC, 0, (size_t)NN * DD, 1.0f);
    // 3) Vt[d][t] = Wv . Xt^T
    gemm_h2<true><<<dim3(NN / TN, DD / TM, BB), 256, GSMEM>>>(
        Wvh, Xt, Vt, NN, CC, 0, (size_t)NN * CC, (size_t)DD * NN, 1.0f);

    // 4) S[i][j] = SCALE * Q . K^T   (f32 out)
    gemm_h2<false><<<dim3(NN / TN, NN / TM, BB), 256, GSMEM>>>(
        Q, K, S, NN, DD, (size_t)NN * DD, (size_t)NN * DD, (size_t)NN * NN, SCALE);

    // 5) softmax rows -> fp16 probs
    softmax_kernel<<<dim3(NN, BB), 256>>>();

    // 6) out[d][t] = Vt . P^T  (f32 out, d-major layout directly)
    gemm_h2<false><<<dim3(NN / TN, DD / TM, BB), 256, GSMEM>>>(
        Vt, Sh, out, NN, NN, (size_t)DD * NN, (size_t)NN * NN, (size_t)DD * NN, 1.0f);

    // 7) scores_out[b][j] = sum_i P[b][i][j]
    zero_scores<<<(BB * NN + 255) / 256, 256>>>(scores_out);
    colsum_kernel<<<dim3(NN / 256, NN / 256, BB), 256>>>(scores_out);
}